// round 5
// baseline (speedup 1.0000x reference)
#include <cuda_runtime.h>
#include <cuda_fp16.h>
#include <cuda_bf16.h>

#define N_NODES 100000
#define D_DIM   64
#define E_EDGES 1600000

#define SCAN_BLOCK 1024
#define N_SCAN_BLOCKS ((N_NODES + SCAN_BLOCK - 1) / SCAN_BLOCK)   // 98

// ---- device scratch (no cudaMalloc allowed; zero-initialized at load) ----
__device__ float  g_adst[N_NODES];          // h[i].w_dst + bias
__device__ float2 g_spack[N_NODES];         // (h[i].w_src, dnorm[i])
__device__ int    g_counts[N_NODES];        // in-degree histogram
                                            // INVARIANT: zero on kernel_launch entry
                                            // (re-zeroed by add_base_kernel each call)
__device__ int    g_offsets[N_NODES + 1];   // CSR row offsets
__device__ int    g_cursor[N_NODES];        // scatter cursors
__device__ int    g_blocksums[N_SCAN_BLOCKS];
__device__ int2   g_edge[E_EDGES];          // CSR payload: (src, coef as bits)
__device__ __half g_hhalf[N_NODES * D_DIM]; // fp16 mirror of h

__device__ __forceinline__ float fast_tanh(float x) {
    float r;
    asm("tanh.approx.f32 %0, %1;" : "=f"(r) : "f"(x));
    return r;
}

// ---------------------------------------------------------------------------
// K1: per-node gate partials (warp per node) + fp16 mirror + FUSED histogram.
// ---------------------------------------------------------------------------
__global__ void node_dots_hist_kernel(const float* __restrict__ h,
                                      const float* __restrict__ dnorm,
                                      const float* __restrict__ gate_w,
                                      const float* __restrict__ gate_b,
                                      const int*   __restrict__ dst)
{
    int tid  = blockIdx.x * blockDim.x + threadIdx.x;
    int warp = tid >> 5;
    int lane = tid & 31;

    if (tid < E_EDGES)
        atomicAdd(&g_counts[dst[tid]], 1);

    if (warp >= N_NODES) return;

    float2 hv = *reinterpret_cast<const float2*>(h + (long long)warp * D_DIM + lane * 2);

    *reinterpret_cast<__half2*>(g_hhalf + (long long)warp * D_DIM + lane * 2) =
        __floats2half2_rn(hv.x, hv.y);

    float2 wd = *reinterpret_cast<const float2*>(gate_w + lane * 2);
    float2 ws = *reinterpret_cast<const float2*>(gate_w + D_DIM + lane * 2);

    float pd = hv.x * wd.x + hv.y * wd.y;
    float ps = hv.x * ws.x + hv.y * ws.y;

    #pragma unroll
    for (int off = 16; off > 0; off >>= 1) {
        pd += __shfl_xor_sync(0xFFFFFFFFu, pd, off);
        ps += __shfl_xor_sync(0xFFFFFFFFu, ps, off);
    }

    if (lane == 0) {
        g_adst[warp]  = pd + gate_b[0];
        g_spack[warp] = make_float2(ps, dnorm[warp]);
    }
}

// ---------------------------------------------------------------------------
// K2: per-block exclusive scan (Hillis-Steele in smem), writes block sums
// ---------------------------------------------------------------------------
__global__ void scan_blocks_kernel()
{
    __shared__ int sdata[SCAN_BLOCK];
    int tid = threadIdx.x;
    int i   = blockIdx.x * SCAN_BLOCK + tid;
    int v   = (i < N_NODES) ? g_counts[i] : 0;
    sdata[tid] = v;
    __syncthreads();

    #pragma unroll
    for (int off = 1; off < SCAN_BLOCK; off <<= 1) {
        int t = (tid >= off) ? sdata[tid - off] : 0;
        __syncthreads();
        sdata[tid] += t;
        __syncthreads();
    }

    if (i < N_NODES) g_offsets[i] = sdata[tid] - v;
    if (tid == SCAN_BLOCK - 1) g_blocksums[blockIdx.x] = sdata[tid];
}

// ---------------------------------------------------------------------------
// K3: add block bases, init cursors, re-zero counts, fix offsets[N].
// ---------------------------------------------------------------------------
__global__ void add_base_kernel()
{
    __shared__ int ssum[128];
    int tid = threadIdx.x;
    if (tid < 128)
        ssum[tid] = (tid < N_SCAN_BLOCKS) ? g_blocksums[tid] : 0;
    __syncthreads();

    #pragma unroll
    for (int off = 1; off < 128; off <<= 1) {
        int t = 0;
        if (tid < 128 && tid >= off) t = ssum[tid - off];
        __syncthreads();
        if (tid < 128) ssum[tid] += t;
        __syncthreads();
    }
    int base = (blockIdx.x == 0) ? 0 : ssum[blockIdx.x - 1];

    int i = blockIdx.x * SCAN_BLOCK + tid;
    if (i < N_NODES) {
        int val = g_offsets[i] + base;
        g_offsets[i] = val;
        g_cursor[i]  = val;
        g_counts[i]  = 0;
    }
    if (blockIdx.x == 0 && tid == 0) g_offsets[N_NODES] = E_EDGES;
}

// ---------------------------------------------------------------------------
// K4: scatter (src, coef) into CSR. 4 edges/thread for MLP on the atomic
// chain; coef computed here (hidden under atomic latency).
// ---------------------------------------------------------------------------
__global__ void csr_scatter_kernel(const int* __restrict__ src,
                                   const int* __restrict__ dst)
{
    int t = blockIdx.x * blockDim.x + threadIdx.x;
    if (t >= E_EDGES / 4) return;

    int4 s4 = reinterpret_cast<const int4*>(src)[t];
    int4 d4 = reinterpret_cast<const int4*>(dst)[t];

    // independent gathers (compiler batches -> MLP)
    float  ad0 = g_adst[d4.x], ad1 = g_adst[d4.y], ad2 = g_adst[d4.z], ad3 = g_adst[d4.w];
    float2 sp0 = g_spack[s4.x], sp1 = g_spack[s4.y], sp2 = g_spack[s4.z], sp3 = g_spack[s4.w];
    float2 dp0 = g_spack[d4.x], dp1 = g_spack[d4.y], dp2 = g_spack[d4.z], dp3 = g_spack[d4.w];

    float c0 = fast_tanh(ad0 + sp0.x) * dp0.y * sp0.y;
    float c1 = fast_tanh(ad1 + sp1.x) * dp1.y * sp1.y;
    float c2 = fast_tanh(ad2 + sp2.x) * dp2.y * sp2.y;
    float c3 = fast_tanh(ad3 + sp3.x) * dp3.y * sp3.y;

    // 4 independent atomic chains in flight
    int p0 = atomicAdd(&g_cursor[d4.x], 1);
    int p1 = atomicAdd(&g_cursor[d4.y], 1);
    int p2 = atomicAdd(&g_cursor[d4.z], 1);
    int p3 = atomicAdd(&g_cursor[d4.w], 1);

    g_edge[p0] = make_int2(s4.x, __float_as_int(c0));
    g_edge[p1] = make_int2(s4.y, __float_as_int(c1));
    g_edge[p2] = make_int2(s4.z, __float_as_int(c2));
    g_edge[p3] = make_int2(s4.w, __float_as_int(c3));
}

// ---------------------------------------------------------------------------
// K5: gather-accumulate. One warp per dst node; per edge: one coalesced 8B
// (src, coef) read + one 128B fp16 h-row. No random scalar gathers, no tanh.
// ---------------------------------------------------------------------------
__global__ void gather_kernel(float* __restrict__ out)
{
    int tid  = blockIdx.x * blockDim.x + threadIdx.x;
    int d    = tid >> 5;
    int lane = tid & 31;
    if (d >= N_NODES) return;

    int beg = g_offsets[d];
    int end = g_offsets[d + 1];

    float accx = 0.f, accy = 0.f;
    const __half* __restrict__ hh = g_hhalf;

    for (int base = beg; base < end; base += 32) {
        int idx = base + lane;
        int s = 0;
        float coef = 0.f;
        if (idx < end) {
            int2 ed = g_edge[idx];
            s = ed.x;
            coef = __int_as_float(ed.y);
        }
        int cnt = end - base;
        if (cnt > 32) cnt = 32;

        int j = 0;
        for (; j + 4 <= cnt; j += 4) {
            int   s0 = __shfl_sync(0xFFFFFFFFu, s, j);
            int   s1 = __shfl_sync(0xFFFFFFFFu, s, j + 1);
            int   s2 = __shfl_sync(0xFFFFFFFFu, s, j + 2);
            int   s3 = __shfl_sync(0xFFFFFFFFu, s, j + 3);
            float c0 = __shfl_sync(0xFFFFFFFFu, coef, j);
            float c1 = __shfl_sync(0xFFFFFFFFu, coef, j + 1);
            float c2 = __shfl_sync(0xFFFFFFFFu, coef, j + 2);
            float c3 = __shfl_sync(0xFFFFFFFFu, coef, j + 3);
            __half2 a0 = *reinterpret_cast<const __half2*>(hh + (long long)s0 * D_DIM + lane * 2);
            __half2 a1 = *reinterpret_cast<const __half2*>(hh + (long long)s1 * D_DIM + lane * 2);
            __half2 a2 = *reinterpret_cast<const __half2*>(hh + (long long)s2 * D_DIM + lane * 2);
            __half2 a3 = *reinterpret_cast<const __half2*>(hh + (long long)s3 * D_DIM + lane * 2);
            float2 f0 = __half22float2(a0);
            float2 f1 = __half22float2(a1);
            float2 f2 = __half22float2(a2);
            float2 f3 = __half22float2(a3);
            accx = fmaf(c0, f0.x, accx); accy = fmaf(c0, f0.y, accy);
            accx = fmaf(c1, f1.x, accx); accy = fmaf(c1, f1.y, accy);
            accx = fmaf(c2, f2.x, accx); accy = fmaf(c2, f2.y, accy);
            accx = fmaf(c3, f3.x, accx); accy = fmaf(c3, f3.y, accy);
        }
        for (; j < cnt; j++) {
            int   sj = __shfl_sync(0xFFFFFFFFu, s, j);
            float cj = __shfl_sync(0xFFFFFFFFu, coef, j);
            __half2 av = *reinterpret_cast<const __half2*>(hh + (long long)sj * D_DIM + lane * 2);
            float2 fv = __half22float2(av);
            accx = fmaf(cj, fv.x, accx);
            accy = fmaf(cj, fv.y, accy);
        }
    }

    *reinterpret_cast<float2*>(out + (long long)d * D_DIM + lane * 2) =
        make_float2(accx, accy);
}

// ---------------------------------------------------------------------------
// Launch (5 kernels)
// ---------------------------------------------------------------------------
extern "C" void kernel_launch(void* const* d_in, const int* in_sizes, int n_in,
                              void* d_out, int out_size)
{
    const float* h      = (const float*)d_in[0];   // (N, 64)
    const float* dnorm  = (const float*)d_in[1];   // (N,)
    const float* gate_w = (const float*)d_in[2];   // (1, 128)
    const float* gate_b = (const float*)d_in[3];   // (1,)
    const int*   src    = (const int*)  d_in[4];   // (E,)
    const int*   dst    = (const int*)  d_in[5];   // (E,)
    float* out = (float*)d_out;                    // (N, 64) float32

    {
        long long total = (long long)N_NODES * 32;
        int blocks = (int)((total + 255) / 256);
        node_dots_hist_kernel<<<blocks, 256>>>(h, dnorm, gate_w, gate_b, dst);
    }
    scan_blocks_kernel<<<N_SCAN_BLOCKS, SCAN_BLOCK>>>();
    add_base_kernel<<<N_SCAN_BLOCKS, SCAN_BLOCK>>>();
    {
        int threads = 256;
        int work = E_EDGES / 4;                    // 400000
        csr_scatter_kernel<<<(work + threads - 1) / threads, threads>>>(src, dst);
    }
    {
        long long total = (long long)N_NODES * 32;
        int blocks = (int)((total + 255) / 256);
        gather_kernel<<<blocks, 256>>>(out);
    }
}